// round 9
// baseline (speedup 1.0000x reference)
#include <cuda_runtime.h>
#include <stdint.h>
#include <math.h>

#define BB     64
#define NCH    129
#define NT     200
#define DM     256
#define DSTATE 16
#define HD     32
#define NL     4
#define DI     512
#define NH     16
#define CONVD  544
#define DPROJ  1072
#define TOK    (BB*NT)   // 12800
#define KPAD   144
#define SMS    20
#define TTILE  20

#define NW_IN  (NL*DPROJ*DM)
#define NW_OUT (NL*DM*DI)
#define GSMEM  (3*2*128*SMS*4)   // 61440 B dynamic smem for 3-stage gemm

// ---------------- scratch ---------------------------------------------------
__device__ float g_xsr[TOK*KPAD];
__device__ float g_mixw[DM*KPAD];
__device__ float g_biasenc[DM];
__device__ float g_bpart[4][DM];
__device__ float g_h[TOK*DM];
__device__ float g_zx[TOK*DPROJ];
__device__ float g_y[TOK*DI];
__device__ float g_o[TOK*DM];
__device__ float g_ss[2*TOK];
__device__ float g_wrnd[NW_IN + NW_OUT];

// ---------------- helpers ---------------------------------------------------
__device__ __forceinline__ float siluf(float x) { return x / (1.f + expf(-x)); }

__device__ __forceinline__ float tf32r(float x) {
    uint32_t r; asm("cvt.rna.tf32.f32 %0, %1;" : "=r"(r) : "f"(x));
    return __uint_as_float(r);
}
__device__ __forceinline__ void mma_tf32(float* c, const uint32_t* a, const uint32_t* b) {
    asm volatile("mma.sync.aligned.m16n8k8.row.col.f32.tf32.tf32.f32 "
        "{%0,%1,%2,%3}, {%4,%5,%6,%7}, {%8,%9}, {%0,%1,%2,%3};"
        : "+f"(c[0]), "+f"(c[1]), "+f"(c[2]), "+f"(c[3])
        : "r"(a[0]), "r"(a[1]), "r"(a[2]), "r"(a[3]), "r"(b[0]), "r"(b[1]));
}
__device__ __forceinline__ void cpa16(uint32_t dst, const void* src, int sz) {
    asm volatile("cp.async.ca.shared.global [%0], [%1], 16, %2;"
                 :: "r"(dst), "l"(src), "r"(sz));
}

// ---------------- TF32 GEMM, 3-stage; optional per-row rms scale ------------
// If ssbuf != null: C[m,n] *= rsqrt((ssbuf[m] + ssbuf[M+m]) / 512 + 1e-5)
__global__ void __launch_bounds__(256, 2)
gemm_tf32(const float* __restrict__ A, const float* __restrict__ W,
          const float* __restrict__ bias, const float* __restrict__ ssbuf,
          float* __restrict__ C, int M, int N, int K) {
    extern __shared__ float dsm[];
    const int bm = blockIdx.y * 128, bn = blockIdx.x * 128;
    const int tid = threadIdx.x, lane = tid & 31, warp = tid >> 5;
    const int wm = (warp & 1) * 64, wn = (warp >> 1) * 32;
    const int r0 = lane >> 2, c0 = lane & 3;

    float acc[4][4][4];
#pragma unroll
    for (int i = 0; i < 4; i++)
#pragma unroll
        for (int j = 0; j < 4; j++)
#pragma unroll
            for (int k = 0; k < 4; k++) acc[i][j][k] = 0.f;

    const int lr = tid >> 2, lc = (tid & 3) * 4;
    const float* Ap0 = A + (size_t)(bm + lr) * K + lc;
    const float* Ap1 = A + (size_t)(bm + lr + 64) * K + lc;
    const int bnr0 = bn + lr, bnr1 = bn + lr + 64;
    const float* Bp0 = W + (size_t)(bnr0 < N ? bnr0 : 0) * K + lc;
    const float* Bp1 = W + (size_t)(bnr1 < N ? bnr1 : 0) * K + lc;
    const int szb0 = bnr0 < N ? 16 : 0, szb1 = bnr1 < N ? 16 : 0;

    const uint32_t base = (uint32_t)__cvta_generic_to_shared(dsm);
    const uint32_t BUFB = 128u * SMS * 4u;
    const uint32_t dof0 = (uint32_t)(lr * SMS + lc) * 4u;
    const uint32_t dof1 = (uint32_t)((lr + 64) * SMS + lc) * 4u;

    const int KT = K >> 4;

#define LOADT(kt, buf)                                                   \
    do {                                                                 \
        int ko = (kt) * 16;                                              \
        uint32_t aA = base + (uint32_t)(buf) * BUFB;                     \
        uint32_t aB = base + (uint32_t)(3 + (buf)) * BUFB;               \
        cpa16(aA + dof0, Ap0 + ko, 16);                                  \
        cpa16(aA + dof1, Ap1 + ko, 16);                                  \
        cpa16(aB + dof0, Bp0 + ko, szb0);                                \
        cpa16(aB + dof1, Bp1 + ko, szb1);                                \
        asm volatile("cp.async.commit_group;");                          \
    } while (0)

    LOADT(0, 0);
    LOADT(1, 1);
    int ib = 2, cb = 0;
    for (int kt = 0; kt < KT; kt++) {
        if (kt < KT - 2) asm volatile("cp.async.wait_group 1;");
        else             asm volatile("cp.async.wait_group 0;");
        __syncthreads();
        if (kt + 2 < KT) {
            LOADT(kt + 2, ib);
            ib = (ib == 2) ? 0 : ib + 1;
        }
        const float* Asb = dsm + (size_t)cb * (128 * SMS);
        const float* Bsb = dsm + (size_t)(3 + cb) * (128 * SMS);
#pragma unroll
        for (int ks = 0; ks < 2; ks++) {
            uint32_t af[4][4], bf[4][2];
#pragma unroll
            for (int mi = 0; mi < 4; mi++) {
                const float* p = &Asb[(wm + mi * 16 + r0) * SMS + ks * 8 + c0];
                af[mi][0] = __float_as_uint(p[0]);
                af[mi][1] = __float_as_uint(p[8 * SMS]);
                af[mi][2] = __float_as_uint(p[4]);
                af[mi][3] = __float_as_uint(p[8 * SMS + 4]);
            }
#pragma unroll
            for (int nj = 0; nj < 4; nj++) {
                const float* p = &Bsb[(wn + nj * 8 + r0) * SMS + ks * 8 + c0];
                bf[nj][0] = __float_as_uint(p[0]);
                bf[nj][1] = __float_as_uint(p[4]);
            }
#pragma unroll
            for (int mi = 0; mi < 4; mi++)
#pragma unroll
                for (int nj = 0; nj < 4; nj++)
                    mma_tf32(acc[mi][nj], af[mi], bf[nj]);
        }
        cb = (cb == 2) ? 0 : cb + 1;
    }
#undef LOADT

#pragma unroll
    for (int mi = 0; mi < 4; mi++) {
        int row = bm + wm + mi * 16 + r0;
        float sc0 = 1.f, sc1 = 1.f;
        if (ssbuf != nullptr) {
            sc0 = rsqrtf((ssbuf[row] + ssbuf[M + row]) * (1.f / DI) + 1e-5f);
            sc1 = rsqrtf((ssbuf[row + 8] + ssbuf[M + row + 8]) * (1.f / DI) + 1e-5f);
        }
#pragma unroll
        for (int nj = 0; nj < 4; nj++) {
            int col = bn + wn + nj * 8 + c0 * 2;
            if (col < N) {
                float b0 = 0.f, b1 = 0.f;
                if (bias != nullptr) { b0 = bias[col]; b1 = bias[col + 1]; }
                float2 v0 = make_float2(acc[mi][nj][0] * sc0 + b0, acc[mi][nj][1] * sc0 + b1);
                float2 v1 = make_float2(acc[mi][nj][2] * sc1 + b0, acc[mi][nj][3] * sc1 + b1);
                *(float2*)&C[(size_t)row * N + col] = v0;
                *(float2*)&C[(size_t)(row + 8) * N + col] = v1;
            }
        }
    }
}

// ---------------- weight prep: round; fold norm_w into out_proj -------------
__global__ void k_roundw(const float* __restrict__ wi, const float* __restrict__ wo,
                         const float* __restrict__ nwp) {
    int idx = blockIdx.x * blockDim.x + threadIdx.x;
    if (idx < NW_IN) {
        g_wrnd[idx] = tf32r(wi[idx]);
    } else if (idx < NW_IN + NW_OUT) {
        int j = idx - NW_IN;
        int l = j / (DM * DI);
        int k = j % DI;
        g_wrnd[idx] = tf32r(wo[j] * nwp[l * DI + k]);
    }
}

// ---------------- encoder ---------------------------------------------------
__global__ void k_sconv(const float* __restrict__ x, const float* __restrict__ w,
                        const float* __restrict__ bias) {
    int c = blockIdx.x, b = blockIdx.y, t = threadIdx.x;
    float v = 0.f;
    if (c < NCH) {
        const float* xr = x + (size_t)(b * NCH + c) * NT;
        float w0 = w[c * 3], w1 = w[c * 3 + 1], w2 = w[c * 3 + 2];
        float xm = (t > 0) ? xr[t - 1] : 0.f;
        float x0 = xr[t];
        float xp = (t < NT - 1) ? xr[t + 1] : 0.f;
        v = tf32r(xm * w0 + x0 * w1 + xp * w2 + bias[c]);
    }
    g_xsr[(size_t)(b * NT + t) * KPAD + c] = v;
}

__global__ void k_mixprep(const float* __restrict__ mw) {
    int idx = blockIdx.x * blockDim.x + threadIdx.x;
    if (idx >= DM * KPAD) return;
    int d = idx / KPAD, k = idx % KPAD;
    g_mixw[idx] = (k < NCH) ? tf32r(mw[d * NCH + k]) : 0.f;
}

// 4 blocks x 256: block covers d in [bid*64, bid*64+64), 4 c-groups
__global__ void k_biasenc(const float* __restrict__ emb, const float* __restrict__ mb) {
    __shared__ float sb[4][64];
    int d = (blockIdx.x << 6) + (threadIdx.x & 63);
    int cg = threadIdx.x >> 6;
    float s = 0.f;
    for (int c = cg; c < NCH; c += 4) s += emb[c * DM + d];
    sb[cg][threadIdx.x & 63] = s;
    __syncthreads();
    if (threadIdx.x < 64) {
        int dd = (blockIdx.x << 6) + threadIdx.x;
        g_biasenc[dd] = mb[dd] +
            (sb[0][threadIdx.x] + sb[1][threadIdx.x] +
             sb[2][threadIdx.x] + sb[3][threadIdx.x]) * (1.f / NCH);
    }
}

// ---------------- warp-per-row layernorm -------------------------------------
__global__ void k_ln(const float* __restrict__ in, const float* __restrict__ res,
                     const float* __restrict__ w, const float* __restrict__ b,
                     float* __restrict__ out) {
    int row = (blockIdx.x * 256 + threadIdx.x) >> 5;
    int lane = threadIdx.x & 31;
    const float4* ip = (const float4*)(in + (size_t)row * DM + lane * 8);
    float4 a0 = ip[0], a1 = ip[1];
    if (res != nullptr) {
        const float4* rp = (const float4*)(res + (size_t)row * DM + lane * 8);
        float4 q0 = rp[0], q1 = rp[1];
        a0.x += q0.x; a0.y += q0.y; a0.z += q0.z; a0.w += q0.w;
        a1.x += q1.x; a1.y += q1.y; a1.z += q1.z; a1.w += q1.w;
    }
    float v[8] = {a0.x, a0.y, a0.z, a0.w, a1.x, a1.y, a1.z, a1.w};
    float s = 0.f, s2 = 0.f;
#pragma unroll
    for (int i = 0; i < 8; i++) { s += v[i]; s2 = fmaf(v[i], v[i], s2); }
#pragma unroll
    for (int o = 16; o > 0; o >>= 1) {
        s  += __shfl_xor_sync(0xffffffffu, s,  o);
        s2 += __shfl_xor_sync(0xffffffffu, s2, o);
    }
    float mean = s * (1.f / DM);
    float var  = s2 * (1.f / DM) - mean * mean;
    float inv  = rsqrtf(var + 1e-5f);
    const float4* wp = (const float4*)(w + lane * 8);
    const float4* bp = (const float4*)(b + lane * 8);
    float4 w0 = wp[0], w1 = wp[1], b0 = bp[0], b1 = bp[1];
    float wv[8] = {w0.x, w0.y, w0.z, w0.w, w1.x, w1.y, w1.z, w1.w};
    float bv[8] = {b0.x, b0.y, b0.z, b0.w, b1.x, b1.y, b1.z, b1.w};
    float o8[8];
#pragma unroll
    for (int i = 0; i < 8; i++) o8[i] = tf32r((v[i] - mean) * inv * wv[i] + bv[i]);
    float4* op = (float4*)(out + (size_t)row * DM + lane * 8);
    op[0] = make_float4(o8[0], o8[1], o8[2], o8[3]);
    op[1] = make_float4(o8[4], o8[5], o8[6], o8[7]);
}

// ---------------- megascan: conv+silu+dt+scan+gate+ssq -----------------------
// grid (BB, 2), block 256; thread = (h, p-half). Writes gated y (tf32-rounded)
// and per-(b,t) partial sum-of-squares to g_ss[half*TOK + bt].
__global__ void k_scan4(const float* __restrict__ cw, const float* __restrict__ cb,
                        const float* __restrict__ dtb, const float* __restrict__ alog,
                        const float* __restrict__ Dsk) {
    const int b = blockIdx.x, half = blockIdx.y;
    const int tid = threadIdx.x;                 // 256
    const int h = tid >> 4, p = (tid & 15) + half * 16;
    const int c = h * HD + p;                    // x-channel in [0,512)
    const int warp = tid >> 5, lane = tid & 31;
    __shared__ float sB[TTILE][16], sC[TTILE][16];
    __shared__ float sA[TTILE][16], sT[TTILE][16];
    __shared__ float wss[8][NT];

    // per-thread conv constants for x channel c
    const float xw0 = cw[c * 4], xw1 = cw[c * 4 + 1];
    const float xw2 = cw[c * 4 + 2], xw3 = cw[c * 4 + 3];
    const float xb = cb[c];
    // stager constants: jj<32 -> B/C conv channel 512+jj; jj in [32,48) -> dt head jj-32
    const int jj = tid & 63, tlb = tid >> 6;
    float sw0 = 0, sw1 = 0, sw2 = 0, sw3 = 0, sbc = 0, sdb = 0, sAe = 0;
    if (jj < 32) {
        int cc = 512 + jj;
        sw0 = cw[cc * 4]; sw1 = cw[cc * 4 + 1];
        sw2 = cw[cc * 4 + 2]; sw3 = cw[cc * 4 + 3];
        sbc = cb[cc];
    } else if (jj < 48) {
        sdb = dtb[jj - 32]; sAe = expf(alog[jj - 32]);
    }
    const float Dh = Dsk[h];
    const int base = b * NT;
    const float* zb = g_zx + (size_t)base * DPROJ;

    float st[DSTATE];
#pragma unroll
    for (int n = 0; n < DSTATE; n++) st[n] = 0.f;
    float hx0 = 0.f, hx1 = 0.f, hx2 = 0.f;   // x-conv halo (z at t-3, t-2, t-1)

    for (int t0 = 0; t0 < NT; t0 += TTILE) {
        float zg[TTILE], zc[TTILE];
#pragma unroll
        for (int tl = 0; tl < TTILE; tl++) {
            zg[tl] = __ldg(zb + (size_t)(t0 + tl) * DPROJ + c);          // gate z
            zc[tl] = __ldg(zb + (size_t)(t0 + tl) * DPROJ + DI + c);     // conv input
        }

        __syncthreads();   // previous tile's smem fully consumed
#pragma unroll
        for (int m = 0; m < 5; m++) {
            const int tl = tlb + 4 * m;
            const int t = t0 + tl;
            if (jj < 32) {
                float acc = sbc;
#pragma unroll
                for (int q = 0; q < 4; q++) {
                    int tt = t - 3 + q;
                    float v = (tt >= 0) ? zb[(size_t)tt * DPROJ + DI + 512 + jj] : 0.f;
                    acc = fmaf(v, q == 0 ? sw0 : q == 1 ? sw1 : q == 2 ? sw2 : sw3, acc);
                }
                float r = siluf(acc);
                if (jj < 16) sB[tl][jj] = r; else sC[tl][jj - 16] = r;
            } else if (jj < 48) {
                float raw = zb[(size_t)t * DPROJ + DI + CONVD + (jj - 32)] + sdb;
                float d = raw > 20.f ? raw : log1pf(expf(raw));
                sT[tl][jj - 32] = d;
                sA[tl][jj - 32] = expf(-d * sAe);
            }
        }
        __syncthreads();

#pragma unroll
        for (int tl = 0; tl < TTILE; tl++) {
            // x-channel causal conv via register halo
            const float v3 = zc[tl];
            const float xp = siluf(xb + xw0 * hx0 + xw1 * hx1 + xw2 * hx2 + xw3 * v3);
            hx0 = hx1; hx1 = hx2; hx2 = v3;

            const float dAh = sA[tl][h];
            const float dtx = sT[tl][h] * xp;
            float a0 = 0.f, a1 = 0.f;
#pragma unroll
            for (int n = 0; n < DSTATE; n += 2) {
                st[n]     = fmaf(dAh, st[n],     dtx * sB[tl][n]);
                st[n + 1] = fmaf(dAh, st[n + 1], dtx * sB[tl][n + 1]);
                a0 = fmaf(st[n],     sC[tl][n],     a0);
                a1 = fmaf(st[n + 1], sC[tl][n + 1], a1);
            }
            const float outv = tf32r((a0 + a1 + xp * Dh) * siluf(zg[tl]));
            g_y[(size_t)(base + t0 + tl) * DI + c] = outv;

            float o2 = outv * outv;
#pragma unroll
            for (int o = 16; o > 0; o >>= 1) o2 += __shfl_xor_sync(0xffffffffu, o2, o);
            if (lane == 0) wss[warp][t0 + tl] = o2;
        }
    }

    __syncthreads();
    for (int t = tid; t < NT; t += 256) {
        float s = 0.f;
#pragma unroll
        for (int w = 0; w < 8; w++) s += wss[w][t];
        g_ss[half * TOK + base + t] = s;
    }
}

// ---------------- fused pool + head ------------------------------------------
__global__ void k_poolhead(const float* __restrict__ w1, const float* __restrict__ b1,
                           const float* __restrict__ w2, const float* __restrict__ b2,
                           float* __restrict__ out) {
    __shared__ float sp[DM];
    __shared__ float sh[4];
    int b = blockIdx.x, tid = threadIdx.x;    // 256
    float s = 0.f;
    for (int t = 0; t < NT; t++) s += g_h[(size_t)(b * NT + t) * DM + tid];
    sp[tid] = s * (1.f / NT);
    __syncthreads();
    if (tid < 128) {
        float acc = b1[tid];
        const float* wr = w1 + tid * DM;
#pragma unroll 8
        for (int k = 0; k < DM; k++) acc = fmaf(sp[k], wr[k], acc);
        float r = fmaxf(acc, 0.f) * w2[tid];
#pragma unroll
        for (int o = 16; o > 0; o >>= 1) r += __shfl_xor_sync(0xffffffffu, r, o);
        int lane = tid & 31, wid = tid >> 5;
        if (lane == 0) sh[wid] = r;
    }
    __syncthreads();
    if (tid == 0) out[b] = sh[0] + sh[1] + sh[2] + sh[3] + b2[0];
}

// ---------------- launch -----------------------------------------------------
extern "C" void kernel_launch(void* const* d_in, const int* in_sizes, int n_in,
                              void* d_out, int out_size) {
    const float* x         = (const float*)d_in[0];
    const float* emb       = (const float*)d_in[1];
    const float* sconv_w   = (const float*)d_in[2];
    const float* sconv_b   = (const float*)d_in[3];
    const float* mixer_w   = (const float*)d_in[4];
    const float* mixer_b   = (const float*)d_in[5];
    const float* enc_ln_w  = (const float*)d_in[6];
    const float* enc_ln_b  = (const float*)d_in[7];
    const float* in_proj_w = (const float*)d_in[8];
    const float* conv_w    = (const float*)d_in[9];
    const float* conv_b    = (const float*)d_in[10];
    const float* dt_bias   = (const float*)d_in[11];
    const float* A_log     = (const float*)d_in[12];
    const float* D_skip    = (const float*)d_in[13];
    const float* norm_w    = (const float*)d_in[14];
    const float* out_proj_w= (const float*)d_in[15];
    const float* ln_w      = (const float*)d_in[16];
    const float* ln_b      = (const float*)d_in[17];
    const float* h1w       = (const float*)d_in[18];
    const float* h1b       = (const float*)d_in[19];
    const float* h2w       = (const float*)d_in[20];
    const float* h2b       = (const float*)d_in[21];
    float* out = (float*)d_out;

    float *xsr, *mixw, *biasenc, *h, *zx, *y, *o, *wrnd, *ss;
    cudaGetSymbolAddress((void**)&xsr,     g_xsr);
    cudaGetSymbolAddress((void**)&mixw,    g_mixw);
    cudaGetSymbolAddress((void**)&biasenc, g_biasenc);
    cudaGetSymbolAddress((void**)&h,       g_h);
    cudaGetSymbolAddress((void**)&zx,      g_zx);
    cudaGetSymbolAddress((void**)&y,       g_y);
    cudaGetSymbolAddress((void**)&o,       g_o);
    cudaGetSymbolAddress((void**)&wrnd,    g_wrnd);
    cudaGetSymbolAddress((void**)&ss,      g_ss);

    cudaFuncSetAttribute(gemm_tf32, cudaFuncAttributeMaxDynamicSharedMemorySize, GSMEM);

    // prep
    k_roundw<<<(NW_IN + NW_OUT + 255) / 256, 256>>>(in_proj_w, out_proj_w, norm_w);
    k_sconv<<<dim3(KPAD, BB), NT>>>(x, sconv_w, sconv_b);
    k_mixprep<<<(DM * KPAD + 255) / 256, 256>>>(mixer_w);
    k_biasenc<<<4, 256>>>(emb, mixer_b);

    // encoder
    gemm_tf32<<<dim3(2, TOK / 128), 256, GSMEM>>>(xsr, mixw, biasenc, nullptr,
                                                  h, TOK, DM, KPAD);
    k_ln<<<TOK / 8, 256>>>(h, nullptr, enc_ln_w, enc_ln_b, h);

    // mamba2 layers
    for (int l = 0; l < NL; l++) {
        gemm_tf32<<<dim3((DPROJ + 127) / 128, TOK / 128), 256, GSMEM>>>(
            h, wrnd + (size_t)l * DPROJ * DM, nullptr, nullptr, zx, TOK, DPROJ, DM);
        k_scan4<<<dim3(BB, 2), 256>>>(conv_w + (size_t)l * CONVD * 4,
                                      conv_b + (size_t)l * CONVD,
                                      dt_bias + l * NH, A_log + l * NH,
                                      D_skip + l * NH);
        gemm_tf32<<<dim3(2, TOK / 128), 256, GSMEM>>>(
            y, wrnd + NW_IN + (size_t)l * DM * DI, nullptr, ss, o, TOK, DM, DI);
        k_ln<<<TOK / 8, 256>>>(o, h, ln_w + l * DM, ln_b + l * DM, h);
    }

    // head
    k_poolhead<<<BB, 256>>>(h1w, h1b, h2w, h2b, out);
}

// round 10
// speedup vs baseline: 1.0461x; 1.0461x over previous
#include <cuda_runtime.h>
#include <stdint.h>
#include <math.h>

#define BB     64
#define NCH    129
#define NT     200
#define DM     256
#define DSTATE 16
#define HD     32
#define NL     4
#define DI     512
#define NH     16
#define CONVD  544
#define DPROJ  1072
#define TOK    (BB*NT)   // 12800
#define KPAD   144
#define SMS    20
#define TTILE  20

#define NW_IN  (NL*DPROJ*DM)
#define NW_OUT (NL*DM*DI)
#define GSMEM  (3*2*128*SMS*4)   // 61440 B dynamic smem for 3-stage gemm

// ---------------- scratch ---------------------------------------------------
__device__ float g_xsr[TOK*KPAD];
__device__ float g_mixw[DM*KPAD];
__device__ float g_biasenc[DM];
__device__ float g_h[TOK*DM];
__device__ float g_zx[TOK*DPROJ];
__device__ float g_y[TOK*DI];
__device__ float g_o[TOK*DM];
__device__ float g_ss[2*TOK];
__device__ float g_wrnd[NW_IN + NW_OUT];

// ---------------- helpers ---------------------------------------------------
__device__ __forceinline__ float siluf(float x) { return x / (1.f + expf(-x)); }

__device__ __forceinline__ float tf32r(float x) {
    uint32_t r; asm("cvt.rna.tf32.f32 %0, %1;" : "=r"(r) : "f"(x));
    return __uint_as_float(r);
}
__device__ __forceinline__ void mma_tf32(float* c, const uint32_t* a, const uint32_t* b) {
    asm volatile("mma.sync.aligned.m16n8k8.row.col.f32.tf32.tf32.f32 "
        "{%0,%1,%2,%3}, {%4,%5,%6,%7}, {%8,%9}, {%0,%1,%2,%3};"
        : "+f"(c[0]), "+f"(c[1]), "+f"(c[2]), "+f"(c[3])
        : "r"(a[0]), "r"(a[1]), "r"(a[2]), "r"(a[3]), "r"(b[0]), "r"(b[1]));
}
__device__ __forceinline__ void cpa16(uint32_t dst, const void* src, int sz) {
    asm volatile("cp.async.ca.shared.global [%0], [%1], 16, %2;"
                 :: "r"(dst), "l"(src), "r"(sz));
}
__device__ __forceinline__ void ldm_x4(uint32_t addr, uint32_t* r) {
    asm volatile("ldmatrix.sync.aligned.m8n8.x4.shared.b16 {%0,%1,%2,%3}, [%4];"
        : "=r"(r[0]), "=r"(r[1]), "=r"(r[2]), "=r"(r[3]) : "r"(addr));
}

// ---------------- TF32 GEMM, 3-stage, ldmatrix fragments --------------------
// If ssbuf != null: C[m,n] *= rsqrt((ssbuf[m] + ssbuf[M+m]) / 512 + 1e-5)
__global__ void __launch_bounds__(256, 2)
gemm_tf32(const float* __restrict__ A, const float* __restrict__ W,
          const float* __restrict__ bias, const float* __restrict__ ssbuf,
          float* __restrict__ C, int M, int N, int K) {
    extern __shared__ float dsm[];
    const int bm = blockIdx.y * 128, bn = blockIdx.x * 128;
    const int tid = threadIdx.x, lane = tid & 31, warp = tid >> 5;
    const int wm = (warp & 1) * 64, wn = (warp >> 1) * 32;
    const int r0 = lane >> 2, c0 = lane & 3;

    float acc[4][4][4];
#pragma unroll
    for (int i = 0; i < 4; i++)
#pragma unroll
        for (int j = 0; j < 4; j++)
#pragma unroll
            for (int k = 0; k < 4; k++) acc[i][j][k] = 0.f;

    const int lr = tid >> 2, lc = (tid & 3) * 4;
    const float* Ap0 = A + (size_t)(bm + lr) * K + lc;
    const float* Ap1 = A + (size_t)(bm + lr + 64) * K + lc;
    const int bnr0 = bn + lr, bnr1 = bn + lr + 64;
    const float* Bp0 = W + (size_t)(bnr0 < N ? bnr0 : 0) * K + lc;
    const float* Bp1 = W + (size_t)(bnr1 < N ? bnr1 : 0) * K + lc;
    const int szb0 = bnr0 < N ? 16 : 0, szb1 = bnr1 < N ? 16 : 0;

    const uint32_t base = (uint32_t)__cvta_generic_to_shared(dsm);
    const uint32_t BUFB = 128u * SMS * 4u;
    const uint32_t dof0 = (uint32_t)(lr * SMS + lc) * 4u;
    const uint32_t dof1 = (uint32_t)((lr + 64) * SMS + lc) * 4u;

    // ldmatrix per-thread fragment addresses (row part fixed per mi/njp)
    const int lane7 = lane & 7;
    const int arow8 = ((lane >> 3) & 1) * 8, acol4 = ((lane >> 4) & 1) * 4;
    const int brow8 = ((lane >> 4) & 1) * 8, bcol4 = ((lane >> 3) & 1) * 4;
    uint32_t aAf[4], aBf[2];
#pragma unroll
    for (int mi = 0; mi < 4; mi++)
        aAf[mi] = base + (uint32_t)(((wm + mi * 16 + lane7 + arow8) * SMS + acol4) * 4);
#pragma unroll
    for (int njp = 0; njp < 2; njp++)
        aBf[njp] = base + 3u * BUFB +
                   (uint32_t)(((wn + njp * 16 + lane7 + brow8) * SMS + bcol4) * 4);

    const int KT = K >> 4;

#define LOADT(kt, buf)                                                   \
    do {                                                                 \
        int ko = (kt) * 16;                                              \
        uint32_t aA = base + (uint32_t)(buf) * BUFB;                     \
        uint32_t aB = base + (uint32_t)(3 + (buf)) * BUFB;               \
        cpa16(aA + dof0, Ap0 + ko, 16);                                  \
        cpa16(aA + dof1, Ap1 + ko, 16);                                  \
        cpa16(aB + dof0, Bp0 + ko, szb0);                                \
        cpa16(aB + dof1, Bp1 + ko, szb1);                                \
        asm volatile("cp.async.commit_group;");                          \
    } while (0)

    LOADT(0, 0);
    LOADT(1, 1);
    int ib = 2, cb = 0;
    for (int kt = 0; kt < KT; kt++) {
        if (kt < KT - 2) asm volatile("cp.async.wait_group 1;");
        else             asm volatile("cp.async.wait_group 0;");
        __syncthreads();
        if (kt + 2 < KT) {
            LOADT(kt + 2, ib);
            ib = (ib == 2) ? 0 : ib + 1;
        }
        const uint32_t cboff = (uint32_t)cb * BUFB;
#pragma unroll
        for (int ks = 0; ks < 2; ks++) {
            uint32_t af[4][4], bf[2][4];
#pragma unroll
            for (int mi = 0; mi < 4; mi++)
                ldm_x4(aAf[mi] + cboff + ks * 32u, af[mi]);
#pragma unroll
            for (int njp = 0; njp < 2; njp++)
                ldm_x4(aBf[njp] + cboff + ks * 32u, bf[njp]);
#pragma unroll
            for (int mi = 0; mi < 4; mi++)
#pragma unroll
                for (int nj = 0; nj < 4; nj++)
                    mma_tf32(acc[mi][nj], af[mi], &bf[nj >> 1][(nj & 1) * 2]);
        }
        cb = (cb == 2) ? 0 : cb + 1;
    }
#undef LOADT

#pragma unroll
    for (int mi = 0; mi < 4; mi++) {
        int row = bm + wm + mi * 16 + r0;
        float sc0 = 1.f, sc1 = 1.f;
        if (ssbuf != nullptr) {
            sc0 = rsqrtf((ssbuf[row] + ssbuf[M + row]) * (1.f / DI) + 1e-5f);
            sc1 = rsqrtf((ssbuf[row + 8] + ssbuf[M + row + 8]) * (1.f / DI) + 1e-5f);
        }
#pragma unroll
        for (int nj = 0; nj < 4; nj++) {
            int col = bn + wn + nj * 8 + c0 * 2;
            if (col < N) {
                float b0 = 0.f, b1 = 0.f;
                if (bias != nullptr) { b0 = bias[col]; b1 = bias[col + 1]; }
                float2 v0 = make_float2(acc[mi][nj][0] * sc0 + b0, acc[mi][nj][1] * sc0 + b1);
                float2 v1 = make_float2(acc[mi][nj][2] * sc1 + b0, acc[mi][nj][3] * sc1 + b1);
                *(float2*)&C[(size_t)row * N + col] = v0;
                *(float2*)&C[(size_t)(row + 8) * N + col] = v1;
            }
        }
    }
}

// ---------------- weight prep: round; fold norm_w into out_proj -------------
__global__ void k_roundw(const float* __restrict__ wi, const float* __restrict__ wo,
                         const float* __restrict__ nwp) {
    int idx = blockIdx.x * blockDim.x + threadIdx.x;
    if (idx < NW_IN) {
        g_wrnd[idx] = tf32r(wi[idx]);
    } else if (idx < NW_IN + NW_OUT) {
        int j = idx - NW_IN;
        int l = j / (DM * DI);
        int k = j % DI;
        g_wrnd[idx] = tf32r(wo[j] * nwp[l * DI + k]);
    }
}

// ---------------- encoder ---------------------------------------------------
__global__ void k_sconv(const float* __restrict__ x, const float* __restrict__ w,
                        const float* __restrict__ bias) {
    int c = blockIdx.x, b = blockIdx.y, t = threadIdx.x;
    float v = 0.f;
    if (c < NCH) {
        const float* xr = x + (size_t)(b * NCH + c) * NT;
        float w0 = w[c * 3], w1 = w[c * 3 + 1], w2 = w[c * 3 + 2];
        float xm = (t > 0) ? xr[t - 1] : 0.f;
        float x0 = xr[t];
        float xp = (t < NT - 1) ? xr[t + 1] : 0.f;
        v = tf32r(xm * w0 + x0 * w1 + xp * w2 + bias[c]);
    }
    g_xsr[(size_t)(b * NT + t) * KPAD + c] = v;
}

__global__ void k_mixprep(const float* __restrict__ mw) {
    int idx = blockIdx.x * blockDim.x + threadIdx.x;
    if (idx >= DM * KPAD) return;
    int d = idx / KPAD, k = idx % KPAD;
    g_mixw[idx] = (k < NCH) ? tf32r(mw[d * NCH + k]) : 0.f;
}

__global__ void k_biasenc(const float* __restrict__ emb, const float* __restrict__ mb) {
    __shared__ float sb[4][64];
    int d = (blockIdx.x << 6) + (threadIdx.x & 63);
    int cg = threadIdx.x >> 6;
    float s = 0.f;
    for (int c = cg; c < NCH; c += 4) s += emb[c * DM + d];
    sb[cg][threadIdx.x & 63] = s;
    __syncthreads();
    if (threadIdx.x < 64) {
        int dd = (blockIdx.x << 6) + threadIdx.x;
        g_biasenc[dd] = mb[dd] +
            (sb[0][threadIdx.x] + sb[1][threadIdx.x] +
             sb[2][threadIdx.x] + sb[3][threadIdx.x]) * (1.f / NCH);
    }
}

// ---------------- warp-per-row layernorm -------------------------------------
__global__ void k_ln(const float* __restrict__ in, const float* __restrict__ res,
                     const float* __restrict__ w, const float* __restrict__ b,
                     float* __restrict__ out) {
    int row = (blockIdx.x * 256 + threadIdx.x) >> 5;
    int lane = threadIdx.x & 31;
    const float4* ip = (const float4*)(in + (size_t)row * DM + lane * 8);
    float4 a0 = ip[0], a1 = ip[1];
    if (res != nullptr) {
        const float4* rp = (const float4*)(res + (size_t)row * DM + lane * 8);
        float4 q0 = rp[0], q1 = rp[1];
        a0.x += q0.x; a0.y += q0.y; a0.z += q0.z; a0.w += q0.w;
        a1.x += q1.x; a1.y += q1.y; a1.z += q1.z; a1.w += q1.w;
    }
    float v[8] = {a0.x, a0.y, a0.z, a0.w, a1.x, a1.y, a1.z, a1.w};
    float s = 0.f, s2 = 0.f;
#pragma unroll
    for (int i = 0; i < 8; i++) { s += v[i]; s2 = fmaf(v[i], v[i], s2); }
#pragma unroll
    for (int o = 16; o > 0; o >>= 1) {
        s  += __shfl_xor_sync(0xffffffffu, s,  o);
        s2 += __shfl_xor_sync(0xffffffffu, s2, o);
    }
    float mean = s * (1.f / DM);
    float var  = s2 * (1.f / DM) - mean * mean;
    float inv  = rsqrtf(var + 1e-5f);
    const float4* wp = (const float4*)(w + lane * 8);
    const float4* bp = (const float4*)(b + lane * 8);
    float4 w0 = wp[0], w1 = wp[1], b0 = bp[0], b1 = bp[1];
    float wv[8] = {w0.x, w0.y, w0.z, w0.w, w1.x, w1.y, w1.z, w1.w};
    float bv[8] = {b0.x, b0.y, b0.z, b0.w, b1.x, b1.y, b1.z, b1.w};
    float o8[8];
#pragma unroll
    for (int i = 0; i < 8; i++) o8[i] = tf32r((v[i] - mean) * inv * wv[i] + bv[i]);
    float4* op = (float4*)(out + (size_t)row * DM + lane * 8);
    op[0] = make_float4(o8[0], o8[1], o8[2], o8[3]);
    op[1] = make_float4(o8[4], o8[5], o8[6], o8[7]);
}

// ---------------- megascan: conv+silu+dt+scan+gate+ssq -----------------------
__global__ void k_scan4(const float* __restrict__ cw, const float* __restrict__ cb,
                        const float* __restrict__ dtb, const float* __restrict__ alog,
                        const float* __restrict__ Dsk) {
    const int b = blockIdx.x, half = blockIdx.y;
    const int tid = threadIdx.x;                 // 256
    const int h = tid >> 4, p = (tid & 15) + half * 16;
    const int c = h * HD + p;
    const int warp = tid >> 5, lane = tid & 31;
    __shared__ float sB[TTILE][16], sC[TTILE][16];
    __shared__ float sA[TTILE][16], sT[TTILE][16];
    __shared__ float wss[8][NT];

    const float xw0 = cw[c * 4], xw1 = cw[c * 4 + 1];
    const float xw2 = cw[c * 4 + 2], xw3 = cw[c * 4 + 3];
    const float xb = cb[c];
    const int jj = tid & 63, tlb = tid >> 6;
    float sw0 = 0, sw1 = 0, sw2 = 0, sw3 = 0, sbc = 0, sdb = 0, sAe = 0;
    if (jj < 32) {
        int cc = 512 + jj;
        sw0 = cw[cc * 4]; sw1 = cw[cc * 4 + 1];
        sw2 = cw[cc * 4 + 2]; sw3 = cw[cc * 4 + 3];
        sbc = cb[cc];
    } else if (jj < 48) {
        sdb = dtb[jj - 32]; sAe = expf(alog[jj - 32]);
    }
    const float Dh = Dsk[h];
    const int base = b * NT;
    const float* zb = g_zx + (size_t)base * DPROJ;

    float st[DSTATE];
#pragma unroll
    for (int n = 0; n < DSTATE; n++) st[n] = 0.f;
    float hx0 = 0.f, hx1 = 0.f, hx2 = 0.f;

    for (int t0 = 0; t0 < NT; t0 += TTILE) {
        float zg[TTILE], zc[TTILE];
#pragma unroll
        for (int tl = 0; tl < TTILE; tl++) {
            zg[tl] = __ldg(zb + (size_t)(t0 + tl) * DPROJ + c);
            zc[tl] = __ldg(zb + (size_t)(t0 + tl) * DPROJ + DI + c);
        }

        __syncthreads();
#pragma unroll
        for (int m = 0; m < 5; m++) {
            const int tl = tlb + 4 * m;
            const int t = t0 + tl;
            if (jj < 32) {
                float acc = sbc;
#pragma unroll
                for (int q = 0; q < 4; q++) {
                    int tt = t - 3 + q;
                    float v = (tt >= 0) ? zb[(size_t)tt * DPROJ + DI + 512 + jj] : 0.f;
                    acc = fmaf(v, q == 0 ? sw0 : q == 1 ? sw1 : q == 2 ? sw2 : sw3, acc);
                }
                float r = siluf(acc);
                if (jj < 16) sB[tl][jj] = r; else sC[tl][jj - 16] = r;
            } else if (jj < 48) {
                float raw = zb[(size_t)t * DPROJ + DI + CONVD + (jj - 32)] + sdb;
                float d = raw > 20.f ? raw : log1pf(expf(raw));
                sT[tl][jj - 32] = d;
                sA[tl][jj - 32] = expf(-d * sAe);
            }
        }
        __syncthreads();

#pragma unroll
        for (int tl = 0; tl < TTILE; tl++) {
            const float v3 = zc[tl];
            const float xp = siluf(xb + xw0 * hx0 + xw1 * hx1 + xw2 * hx2 + xw3 * v3);
            hx0 = hx1; hx1 = hx2; hx2 = v3;

            const float dAh = sA[tl][h];
            const float dtx = sT[tl][h] * xp;
            float a0 = 0.f, a1 = 0.f;
#pragma unroll
            for (int n = 0; n < DSTATE; n += 2) {
                st[n]     = fmaf(dAh, st[n],     dtx * sB[tl][n]);
                st[n + 1] = fmaf(dAh, st[n + 1], dtx * sB[tl][n + 1]);
                a0 = fmaf(st[n],     sC[tl][n],     a0);
                a1 = fmaf(st[n + 1], sC[tl][n + 1], a1);
            }
            const float outv = tf32r((a0 + a1 + xp * Dh) * siluf(zg[tl]));
            g_y[(size_t)(base + t0 + tl) * DI + c] = outv;

            float o2 = outv * outv;
#pragma unroll
            for (int o = 16; o > 0; o >>= 1) o2 += __shfl_xor_sync(0xffffffffu, o2, o);
            if (lane == 0) wss[warp][t0 + tl] = o2;
        }
    }

    __syncthreads();
    for (int t = tid; t < NT; t += 256) {
        float s = 0.f;
#pragma unroll
        for (int w = 0; w < 8; w++) s += wss[w][t];
        g_ss[half * TOK + base + t] = s;
    }
}

// ---------------- fused pool + head ------------------------------------------
__global__ void k_poolhead(const float* __restrict__ w1, const float* __restrict__ b1,
                           const float* __restrict__ w2, const float* __restrict__ b2,
                           float* __restrict__ out) {
    __shared__ float sp[DM];
    __shared__ float sh[4];
    int b = blockIdx.x, tid = threadIdx.x;    // 256
    float s = 0.f;
    for (int t = 0; t < NT; t++) s += g_h[(size_t)(b * NT + t) * DM + tid];
    sp[tid] = s * (1.f / NT);
    __syncthreads();
    if (tid < 128) {
        float acc = b1[tid];
        const float* wr = w1 + tid * DM;
#pragma unroll 8
        for (int k = 0; k < DM; k++) acc = fmaf(sp[k], wr[k], acc);
        float r = fmaxf(acc, 0.f) * w2[tid];
#pragma unroll
        for (int o = 16; o > 0; o >>= 1) r += __shfl_xor_sync(0xffffffffu, r, o);
        int lane = tid & 31, wid = tid >> 5;
        if (lane == 0) sh[wid] = r;
    }
    __syncthreads();
    if (tid == 0) out[b] = sh[0] + sh[1] + sh[2] + sh[3] + b2[0];
}

// ---------------- launch -----------------------------------------------------
extern "C" void kernel_launch(void* const* d_in, const int* in_sizes, int n_in,
                              void* d_out, int out_size) {
    const float* x         = (const float*)d_in[0];
    const float* emb       = (const float*)d_in[1];
    const float* sconv_w   = (const float*)d_in[2];
    const float* sconv_b   = (const float*)d_in[3];
    const float* mixer_w   = (const float*)d_in[4];
    const float* mixer_b   = (const float*)d_in[5];
    const float* enc_ln_w  = (const float*)d_in[6];
    const float* enc_ln_b  = (const float*)d_in[7];
    const float* in_proj_w = (const float*)d_in[8];
    const float* conv_w    = (const float*)d_in[9];
    const float* conv_b    = (const float*)d_in[10];
    const float* dt_bias   = (const float*)d_in[11];
    const float* A_log     = (const float*)d_in[12];
    const float* D_skip    = (const float*)d_in[13];
    const float* norm_w    = (const float*)d_in[14];
    const float* out_proj_w= (const float*)d_in[15];
    const float* ln_w      = (const float*)d_in[16];
    const float* ln_b      = (const float*)d_in[17];
    const float* h1w       = (const float*)d_in[18];
    const float* h1b       = (const float*)d_in[19];
    const float* h2w       = (const float*)d_in[20];
    const float* h2b       = (const float*)d_in[21];
    float* out = (float*)d_out;

    float *xsr, *mixw, *biasenc, *h, *zx, *y, *o, *wrnd, *ss;
    cudaGetSymbolAddress((void**)&xsr,     g_xsr);
    cudaGetSymbolAddress((void**)&mixw,    g_mixw);
    cudaGetSymbolAddress((void**)&biasenc, g_biasenc);
    cudaGetSymbolAddress((void**)&h,       g_h);
    cudaGetSymbolAddress((void**)&zx,      g_zx);
    cudaGetSymbolAddress((void**)&y,       g_y);
    cudaGetSymbolAddress((void**)&o,       g_o);
    cudaGetSymbolAddress((void**)&wrnd,    g_wrnd);
    cudaGetSymbolAddress((void**)&ss,      g_ss);

    cudaFuncSetAttribute(gemm_tf32, cudaFuncAttributeMaxDynamicSharedMemorySize, GSMEM);

    // prep
    k_roundw<<<(NW_IN + NW_OUT + 255) / 256, 256>>>(in_proj_w, out_proj_w, norm_w);
    k_sconv<<<dim3(KPAD, BB), NT>>>(x, sconv_w, sconv_b);
    k_mixprep<<<(DM * KPAD + 255) / 256, 256>>>(mixer_w);
    k_biasenc<<<4, 256>>>(emb, mixer_b);

    // encoder
    gemm_tf32<<<dim3(2, TOK / 128), 256, GSMEM>>>(xsr, mixw, biasenc, nullptr,
                                                  h, TOK, DM, KPAD);
    k_ln<<<TOK / 8, 256>>>(h, nullptr, enc_ln_w, enc_ln_b, h);

    // mamba2 layers
    for (int l = 0; l < NL; l++) {
        gemm_tf32<<<dim3((DPROJ + 127) / 128, TOK / 128), 256, GSMEM>>>(
            h, wrnd + (size_t)l * DPROJ * DM, nullptr, nullptr, zx, TOK, DPROJ, DM);
        k_scan4<<<dim3(BB, 2), 256>>>(conv_w + (size_t)l * CONVD * 4,
                                      conv_b + (size_t)l * CONVD,
                                      dt_bias + l * NH, A_log + l * NH,
                                      D_skip + l * NH);
        gemm_tf32<<<dim3(2, TOK / 128), 256, GSMEM>>>(
            y, wrnd + NW_IN + (size_t)l * DM * DI, nullptr, ss, o, TOK, DM, DI);
        k_ln<<<TOK / 8, 256>>>(o, h, ln_w + l * DM, ln_b + l * DM, h);
    }

    // head
    k_poolhead<<<BB, 256>>>(h1w, h1b, h2w, h2b, out);
}

// round 11
// speedup vs baseline: 1.3038x; 1.2463x over previous
#include <cuda_runtime.h>
#include <cuda_fp16.h>
#include <stdint.h>
#include <math.h>

#define BB     64
#define NCH    129
#define NT     200
#define DM     256
#define DSTATE 16
#define HD     32
#define NL     4
#define DI     512
#define NH     16
#define CONVD  544
#define DPROJ  1072
#define TOK    (BB*NT)   // 12800
#define KPAD   144
#define SMH    24        // smem row stride in halfs (16 + 8 pad) -> ldmatrix conflict-free
#define TTILE  20

#define NW_IN  (NL*DPROJ*DM)
#define NW_OUT (NL*DM*DI)
#define STAGEB (128*SMH*2)            // 6144 B per matrix per stage
#define GSMEM  (4*2*STAGEB)           // 49152 B: 4 stages x (A,B)

// ---------------- scratch ---------------------------------------------------
__device__ __align__(16) __half g_xsr[TOK*KPAD];
__device__ __align__(16) __half g_mixw[DM*KPAD];
__device__ float  g_biasenc[DM];
__device__ __align__(16) __half g_h[TOK*DM];
__device__ float  g_zx[TOK*DPROJ];
__device__ __align__(16) __half g_y[TOK*DI];
__device__ float  g_o[TOK*DM];
__device__ float  g_ss[2*TOK];
__device__ __align__(16) __half g_wrnd[NW_IN + NW_OUT];

// ---------------- helpers ---------------------------------------------------
__device__ __forceinline__ float siluf(float x) { return x / (1.f + expf(-x)); }

__device__ __forceinline__ void mma_f16(float* c, const uint32_t* a, const uint32_t* b) {
    asm volatile("mma.sync.aligned.m16n8k16.row.col.f32.f16.f16.f32 "
        "{%0,%1,%2,%3}, {%4,%5,%6,%7}, {%8,%9}, {%0,%1,%2,%3};"
        : "+f"(c[0]), "+f"(c[1]), "+f"(c[2]), "+f"(c[3])
        : "r"(a[0]), "r"(a[1]), "r"(a[2]), "r"(a[3]), "r"(b[0]), "r"(b[1]));
}
__device__ __forceinline__ void cpa16(uint32_t dst, const void* src, int sz) {
    asm volatile("cp.async.ca.shared.global [%0], [%1], 16, %2;"
                 :: "r"(dst), "l"(src), "r"(sz));
}
__device__ __forceinline__ void ldm_x4(uint32_t addr, uint32_t* r) {
    asm volatile("ldmatrix.sync.aligned.m8n8.x4.shared.b16 {%0,%1,%2,%3}, [%4];"
        : "=r"(r[0]), "=r"(r[1]), "=r"(r[2]), "=r"(r[3]) : "r"(addr));
}

// ---------------- FP16 GEMM, 4-stage, ldmatrix, fp32 accum ------------------
// C[m,n] = sum_k A[m,k]*W[n,k]; A: MxK halfs, W: NxK halfs, C fp32.
// If ssbuf != null: C[m,:] *= rsqrt((ssbuf[m] + ssbuf[M+m]) / 512 + 1e-5)
__global__ void __launch_bounds__(256, 2)
gemm_f16(const __half* __restrict__ A, const __half* __restrict__ W,
         const float* __restrict__ bias, const float* __restrict__ ssbuf,
         float* __restrict__ C, int M, int N, int K) {
    extern __shared__ __half dsm[];
    const int bm = blockIdx.y * 128, bn = blockIdx.x * 128;
    const int tid = threadIdx.x, lane = tid & 31, warp = tid >> 5;
    const int wm = (warp & 1) * 64, wn = (warp >> 1) * 32;
    const int r0 = lane >> 2, c0 = lane & 3;

    float acc[4][4][4];
#pragma unroll
    for (int i = 0; i < 4; i++)
#pragma unroll
        for (int j = 0; j < 4; j++)
#pragma unroll
            for (int k = 0; k < 4; k++) acc[i][j][k] = 0.f;

    // loader: thread -> row=tid>>1 (0..127), 16B chunk=(tid&1)
    const int lrow = tid >> 1, lch = (tid & 1) * 8;     // chunk offset in halfs
    const __half* Ap = A + (size_t)(bm + lrow) * K + lch;
    const int bnr = bn + lrow;
    const __half* Bp = W + (size_t)(bnr < N ? bnr : 0) * K + lch;
    const int szb = bnr < N ? 16 : 0;

    const uint32_t base = (uint32_t)__cvta_generic_to_shared(dsm);
    const uint32_t dof = (uint32_t)(lrow * SMH + lch) * 2u;

    // ldmatrix fragment addresses
    const int lane7 = lane & 7;
    const int arow8 = ((lane >> 3) & 1) * 8, acol8 = ((lane >> 4) & 1) * 8;
    const int brow8 = ((lane >> 4) & 1) * 8, bcol8 = ((lane >> 3) & 1) * 8;
    uint32_t aAf[4], aBf[2];
#pragma unroll
    for (int mi = 0; mi < 4; mi++)
        aAf[mi] = base + (uint32_t)(((wm + mi * 16 + lane7 + arow8) * SMH + acol8) * 2);
#pragma unroll
    for (int njp = 0; njp < 2; njp++)
        aBf[njp] = base + 4u * STAGEB +
                   (uint32_t)(((wn + njp * 16 + lane7 + brow8) * SMH + bcol8) * 2);

    const int KT = K >> 4;

#define LOADT(kt, buf)                                                   \
    do {                                                                 \
        int ko = (kt) * 16;                                              \
        uint32_t aA = base + (uint32_t)(buf) * STAGEB;                   \
        uint32_t aB = base + (uint32_t)(4 + (buf)) * STAGEB;             \
        cpa16(aA + dof, Ap + ko, 16);                                    \
        cpa16(aB + dof, Bp + ko, szb);                                   \
        asm volatile("cp.async.commit_group;");                          \
    } while (0)

    LOADT(0, 0);
    if (KT > 1) LOADT(1, 1);
    if (KT > 2) LOADT(2, 2);
    for (int kt = 0; kt < KT; kt++) {
        if (kt < KT - 3) asm volatile("cp.async.wait_group 2;");
        else             asm volatile("cp.async.wait_group 0;");
        __syncthreads();
        if (kt + 3 < KT) LOADT(kt + 3, (kt + 3) & 3);
        const uint32_t cboff = (uint32_t)(kt & 3) * STAGEB;

        uint32_t af[4][4], bf[2][4];
#pragma unroll
        for (int mi = 0; mi < 4; mi++) ldm_x4(aAf[mi] + cboff, af[mi]);
#pragma unroll
        for (int njp = 0; njp < 2; njp++) ldm_x4(aBf[njp] + cboff, bf[njp]);
#pragma unroll
        for (int mi = 0; mi < 4; mi++)
#pragma unroll
            for (int nj = 0; nj < 4; nj++)
                mma_f16(acc[mi][nj], af[mi], &bf[nj >> 1][(nj & 1) * 2]);
    }
#undef LOADT

#pragma unroll
    for (int mi = 0; mi < 4; mi++) {
        int row = bm + wm + mi * 16 + r0;
        float sc0 = 1.f, sc1 = 1.f;
        if (ssbuf != nullptr) {
            sc0 = rsqrtf((ssbuf[row] + ssbuf[M + row]) * (1.f / DI) + 1e-5f);
            sc1 = rsqrtf((ssbuf[row + 8] + ssbuf[M + row + 8]) * (1.f / DI) + 1e-5f);
        }
#pragma unroll
        for (int nj = 0; nj < 4; nj++) {
            int col = bn + wn + nj * 8 + c0 * 2;
            if (col < N) {
                float b0 = 0.f, b1 = 0.f;
                if (bias != nullptr) { b0 = bias[col]; b1 = bias[col + 1]; }
                float2 v0 = make_float2(acc[mi][nj][0] * sc0 + b0, acc[mi][nj][1] * sc0 + b1);
                float2 v1 = make_float2(acc[mi][nj][2] * sc1 + b0, acc[mi][nj][3] * sc1 + b1);
                *(float2*)&C[(size_t)row * N + col] = v0;
                *(float2*)&C[(size_t)(row + 8) * N + col] = v1;
            }
        }
    }
}

// ---------------- weight prep: half-round; fold norm_w into out_proj --------
__global__ void k_prepw(const float* __restrict__ wi, const float* __restrict__ wo,
                        const float* __restrict__ nwp) {
    int idx = blockIdx.x * blockDim.x + threadIdx.x;
    if (idx < NW_IN) {
        g_wrnd[idx] = __float2half_rn(wi[idx]);
    } else if (idx < NW_IN + NW_OUT) {
        int j = idx - NW_IN;
        int l = j / (DM * DI);
        int k = j % DI;
        g_wrnd[idx] = __float2half_rn(wo[j] * nwp[l * DI + k]);
    }
}

// ---------------- encoder ---------------------------------------------------
__global__ void k_sconv(const float* __restrict__ x, const float* __restrict__ w,
                        const float* __restrict__ bias) {
    int c = blockIdx.x, b = blockIdx.y, t = threadIdx.x;
    float v = 0.f;
    if (c < NCH) {
        const float* xr = x + (size_t)(b * NCH + c) * NT;
        float w0 = w[c * 3], w1 = w[c * 3 + 1], w2 = w[c * 3 + 2];
        float xm = (t > 0) ? xr[t - 1] : 0.f;
        float x0 = xr[t];
        float xp = (t < NT - 1) ? xr[t + 1] : 0.f;
        v = xm * w0 + x0 * w1 + xp * w2 + bias[c];
    }
    g_xsr[(size_t)(b * NT + t) * KPAD + c] = __float2half_rn(v);
}

__global__ void k_mixprep(const float* __restrict__ mw) {
    int idx = blockIdx.x * blockDim.x + threadIdx.x;
    if (idx >= DM * KPAD) return;
    int d = idx / KPAD, k = idx % KPAD;
    g_mixw[idx] = __float2half_rn((k < NCH) ? mw[d * NCH + k] : 0.f);
}

__global__ void k_biasenc(const float* __restrict__ emb, const float* __restrict__ mb) {
    __shared__ float sb[4][64];
    int d = (blockIdx.x << 6) + (threadIdx.x & 63);
    int cg = threadIdx.x >> 6;
    float s = 0.f;
    for (int c = cg; c < NCH; c += 4) s += emb[c * DM + d];
    sb[cg][threadIdx.x & 63] = s;
    __syncthreads();
    if (threadIdx.x < 64) {
        int dd = (blockIdx.x << 6) + threadIdx.x;
        g_biasenc[dd] = mb[dd] +
            (sb[0][threadIdx.x] + sb[1][threadIdx.x] +
             sb[2][threadIdx.x] + sb[3][threadIdx.x]) * (1.f / NCH);
    }
}

// ---------------- warp-per-row layernorm: fp32 in (+half res) -> half out ---
union Pk8 { uint4 u; __half h[8]; };

__global__ void k_ln(const float* __restrict__ in, const __half* __restrict__ res,
                     const float* __restrict__ w, const float* __restrict__ b,
                     __half* __restrict__ out) {
    int row = (blockIdx.x * 256 + threadIdx.x) >> 5;
    int lane = threadIdx.x & 31;
    const float4* ip = (const float4*)(in + (size_t)row * DM + lane * 8);
    float4 a0 = ip[0], a1 = ip[1];
    float v[8] = {a0.x, a0.y, a0.z, a0.w, a1.x, a1.y, a1.z, a1.w};
    if (res != nullptr) {
        Pk8 r;
        r.u = *(const uint4*)(res + (size_t)row * DM + lane * 8);
#pragma unroll
        for (int i = 0; i < 8; i++) v[i] += __half2float(r.h[i]);
    }
    float s = 0.f, s2 = 0.f;
#pragma unroll
    for (int i = 0; i < 8; i++) { s += v[i]; s2 = fmaf(v[i], v[i], s2); }
#pragma unroll
    for (int o = 16; o > 0; o >>= 1) {
        s  += __shfl_xor_sync(0xffffffffu, s,  o);
        s2 += __shfl_xor_sync(0xffffffffu, s2, o);
    }
    float mean = s * (1.f / DM);
    float var  = s2 * (1.f / DM) - mean * mean;
    float inv  = rsqrtf(var + 1e-5f);
    const float4* wp = (const float4*)(w + lane * 8);
    const float4* bp = (const float4*)(b + lane * 8);
    float4 w0 = wp[0], w1 = wp[1], b0 = bp[0], b1 = bp[1];
    float wv[8] = {w0.x, w0.y, w0.z, w0.w, w1.x, w1.y, w1.z, w1.w};
    float bv[8] = {b0.x, b0.y, b0.z, b0.w, b1.x, b1.y, b1.z, b1.w};
    Pk8 o8;
#pragma unroll
    for (int i = 0; i < 8; i++)
        o8.h[i] = __float2half_rn((v[i] - mean) * inv * wv[i] + bv[i]);
    *(uint4*)(out + (size_t)row * DM + lane * 8) = o8.u;
}

// ---------------- megascan: conv+silu+dt+scan+gate+ssq -----------------------
__global__ void k_scan4(const float* __restrict__ cw, const float* __restrict__ cb,
                        const float* __restrict__ dtb, const float* __restrict__ alog,
                        const float* __restrict__ Dsk) {
    const int b = blockIdx.x, half = blockIdx.y;
    const int tid = threadIdx.x;                 // 256
    const int h = tid >> 4, p = (tid & 15) + half * 16;
    const int c = h * HD + p;
    const int warp = tid >> 5, lane = tid & 31;
    __shared__ float sB[TTILE][16], sC[TTILE][16];
    __shared__ float sA[TTILE][16], sT[TTILE][16];
    __shared__ float wss[8][NT];

    const float xw0 = cw[c * 4], xw1 = cw[c * 4 + 1];
    const float xw2 = cw[c * 4 + 2], xw3 = cw[c * 4 + 3];
    const float xb = cb[c];
    const int jj = tid & 63, tlb = tid >> 6;
    float sw0 = 0, sw1 = 0, sw2 = 0, sw3 = 0, sbc = 0, sdb = 0, sAe = 0;
    if (jj < 32) {
        int cc = 512 + jj;
        sw0 = cw[cc * 4]; sw1 = cw[cc * 4 + 1];
        sw2 = cw[cc * 4 + 2]; sw3 = cw[cc * 4 + 3];
        sbc = cb[cc];
    } else if (jj < 48) {
        sdb = dtb[jj - 32]; sAe = expf(alog[jj - 32]);
    }
    const float Dh = Dsk[h];
    const int base = b * NT;
    const float* zb = g_zx + (size_t)base * DPROJ;

    float st[DSTATE];
#pragma unroll
    for (int n = 0; n < DSTATE; n++) st[n] = 0.f;
    float hx0 = 0.f, hx1 = 0.f, hx2 = 0.f;

    for (int t0 = 0; t0 < NT; t0 += TTILE) {
        float zg[TTILE], zc[TTILE];
#pragma unroll
        for (int tl = 0; tl < TTILE; tl++) {
            zg[tl] = __ldg(zb + (size_t)(t0 + tl) * DPROJ + c);
            zc[tl] = __ldg(zb + (size_t)(t0 + tl) * DPROJ + DI + c);
        }

        __syncthreads();
#pragma unroll
        for (int m = 0; m < 5; m++) {
            const int tl = tlb + 4 * m;
            const int t = t0 + tl;
            if (jj < 32) {
                float acc = sbc;
#pragma unroll
                for (int q = 0; q < 4; q++) {
                    int tt = t - 3 + q;
                    float v = (tt >= 0) ? zb[(size_t)tt * DPROJ + DI + 512 + jj] : 0.f;
                    acc = fmaf(v, q == 0 ? sw0 : q == 1 ? sw1 : q == 2 ? sw2 : sw3, acc);
                }
                float r = siluf(acc);
                if (jj < 16) sB[tl][jj] = r; else sC[tl][jj - 16] = r;
            } else if (jj < 48) {
                float raw = zb[(size_t)t * DPROJ + DI + CONVD + (jj - 32)] + sdb;
                float d = raw > 20.f ? raw : log1pf(expf(raw));
                sT[tl][jj - 32] = d;
                sA[tl][jj - 32] = expf(-d * sAe);
            }
        }
        __syncthreads();

#pragma unroll
        for (int tl = 0; tl < TTILE; tl++) {
            const float v3 = zc[tl];
            const float xp = siluf(xb + xw0 * hx0 + xw1 * hx1 + xw2 * hx2 + xw3 * v3);
            hx0 = hx1; hx1 = hx2; hx2 = v3;

            const float dAh = sA[tl][h];
            const float dtx = sT[tl][h] * xp;
            float a0 = 0.f, a1 = 0.f;
#pragma unroll
            for (int n = 0; n < DSTATE; n += 2) {
                st[n]     = fmaf(dAh, st[n],     dtx * sB[tl][n]);
                st[n + 1] = fmaf(dAh, st[n + 1], dtx * sB[tl][n + 1]);
                a0 = fmaf(st[n],     sC[tl][n],     a0);
                a1 = fmaf(st[n + 1], sC[tl][n + 1], a1);
            }
            const __half hv = __float2half_rn((a0 + a1 + xp * Dh) * siluf(zg[tl]));
            g_y[(size_t)(base + t0 + tl) * DI + c] = hv;

            const float ov = __half2float(hv);
            float o2 = ov * ov;
#pragma unroll
            for (int o = 16; o > 0; o >>= 1) o2 += __shfl_xor_sync(0xffffffffu, o2, o);
            if (lane == 0) wss[warp][t0 + tl] = o2;
        }
    }

    __syncthreads();
    for (int t = tid; t < NT; t += 256) {
        float s = 0.f;
#pragma unroll
        for (int w = 0; w < 8; w++) s += wss[w][t];
        g_ss[half * TOK + base + t] = s;
    }
}

// ---------------- fused pool + head ------------------------------------------
__global__ void k_poolhead(const float* __restrict__ w1, const float* __restrict__ b1,
                           const float* __restrict__ w2, const float* __restrict__ b2,
                           float* __restrict__ out) {
    __shared__ float sp[DM];
    __shared__ float sh[4];
    int b = blockIdx.x, tid = threadIdx.x;    // 256
    float s = 0.f;
    for (int t = 0; t < NT; t++) s += __half2float(g_h[(size_t)(b * NT + t) * DM + tid]);
    sp[tid] = s * (1.f / NT);
    __syncthreads();
    if (tid < 128) {
        float acc = b1[tid];
        const float* wr = w1 + tid * DM;
#pragma unroll 8
        for (int k = 0; k < DM; k++) acc = fmaf(sp[k], wr[k], acc);
        float r = fmaxf(acc, 0.f) * w2[tid];
#pragma unroll
        for (int o = 16; o > 0; o >>= 1) r += __shfl_xor_sync(0xffffffffu, r, o);
        int lane = tid & 31, wid = tid >> 5;
        if (lane == 0) sh[wid] = r;
    }
    __syncthreads();
    if (tid == 0) out[b] = sh[0] + sh[1] + sh[2] + sh[3] + b2[0];
}

// ---------------- launch -----------------------------------------------------
extern "C" void kernel_launch(void* const* d_in, const int* in_sizes, int n_in,
                              void* d_out, int out_size) {
    const float* x         = (const float*)d_in[0];
    const float* emb       = (const float*)d_in[1];
    const float* sconv_w   = (const float*)d_in[2];
    const float* sconv_b   = (const float*)d_in[3];
    const float* mixer_w   = (const float*)d_in[4];
    const float* mixer_b   = (const float*)d_in[5];
    const float* enc_ln_w  = (const float*)d_in[6];
    const float* enc_ln_b  = (const float*)d_in[7];
    const float* in_proj_w = (const float*)d_in[8];
    const float* conv_w    = (const float*)d_in[9];
    const float* conv_b    = (const float*)d_in[10];
    const float* dt_bias   = (const float*)d_in[11];
    const float* A_log     = (const float*)d_in[12];
    const float* D_skip    = (const float*)d_in[13];
    const float* norm_w    = (const float*)d_in[14];
    const float* out_proj_w= (const float*)d_in[15];
    const float* ln_w      = (const float*)d_in[16];
    const float* ln_b      = (const float*)d_in[17];
    const float* h1w       = (const float*)d_in[18];
    const float* h1b       = (const float*)d_in[19];
    const float* h2w       = (const float*)d_in[20];
    const float* h2b       = (const float*)d_in[21];
    float* out = (float*)d_out;

    __half *xsr, *mixw, *h, *y, *wrnd;
    float *biasenc, *zx, *o, *ss;
    cudaGetSymbolAddress((void**)&xsr,     g_xsr);
    cudaGetSymbolAddress((void**)&mixw,    g_mixw);
    cudaGetSymbolAddress((void**)&biasenc, g_biasenc);
    cudaGetSymbolAddress((void**)&h,       g_h);
    cudaGetSymbolAddress((void**)&zx,      g_zx);
    cudaGetSymbolAddress((void**)&y,       g_y);
    cudaGetSymbolAddress((void**)&o,       g_o);
    cudaGetSymbolAddress((void**)&wrnd,    g_wrnd);
    cudaGetSymbolAddress((void**)&ss,      g_ss);

    cudaFuncSetAttribute(gemm_f16, cudaFuncAttributeMaxDynamicSharedMemorySize, GSMEM);

    // prep
    k_prepw<<<(NW_IN + NW_OUT + 255) / 256, 256>>>(in_proj_w, out_proj_w, norm_w);
    k_sconv<<<dim3(KPAD, BB), NT>>>(x, sconv_w, sconv_b);
    k_mixprep<<<(DM * KPAD + 255) / 256, 256>>>(mixer_w);
    k_biasenc<<<4, 256>>>(emb, mixer_b);

    // encoder: gemm -> o (fp32), ln -> h (half)
    gemm_f16<<<dim3(2, TOK / 128), 256, GSMEM>>>(xsr, mixw, biasenc, nullptr,
                                                 o, TOK, DM, KPAD);
    k_ln<<<TOK / 8, 256>>>(o, nullptr, enc_ln_w, enc_ln_b, h);

    // mamba2 layers
    for (int l = 0; l < NL; l++) {
        gemm_f16<<<dim3((DPROJ + 127) / 128, TOK / 128), 256, GSMEM>>>(
            h, wrnd + (size_t)l * DPROJ * DM, nullptr, nullptr, zx, TOK, DPROJ, DM);
        k_scan4<<<dim3(BB, 2), 256>>>(conv_w + (size_t)l * CONVD * 4,
                                      conv_b + (size_t)l * CONVD,
                                      dt_bias + l * NH, A_log + l * NH,
                                      D_skip + l * NH);
        gemm_f16<<<dim3(2, TOK / 128), 256, GSMEM>>>(
            y, wrnd + NW_IN + (size_t)l * DM * DI, nullptr, ss, o, TOK, DM, DI);
        k_ln<<<TOK / 8, 256>>>(o, h, ln_w + l * DM, ln_b + l * DM, h);
    }

    // head
    k_poolhead<<<BB, 256>>>(h1w, h1b, h2w, h2b, out);
}

// round 12
// speedup vs baseline: 1.3887x; 1.0651x over previous
#include <cuda_runtime.h>
#include <cuda_fp16.h>
#include <stdint.h>
#include <math.h>

#define BB     64
#define NCH    129
#define NT     200
#define DM     256
#define DSTATE 16
#define HD     32
#define NL     4
#define DI     512
#define NH     16
#define CONVD  544
#define DPROJ  1072
#define TOK    (BB*NT)   // 12800
#define KPAD   144
#define SMH    24        // smem row stride in halfs -> ldmatrix conflict-free
#define TTILE  20
#define TSEG   25        // bc precompute segment

#define NW_IN  (NL*DPROJ*DM)
#define NW_OUT (NL*DM*DI)
#define STAGEB (128*SMH*2)            // 6144 B per matrix per stage
#define GSMEM  (4*2*STAGEB)           // 49152 B: 4 stages x (A,B)

// ---------------- scratch ---------------------------------------------------
__device__ __align__(16) __half g_xsr[TOK*KPAD];
__device__ __align__(16) __half g_mixw[DM*KPAD];
__device__ float  g_biasenc[DM];
__device__ __align__(16) __half g_h[TOK*DM];
__device__ float  g_zx[TOK*DPROJ];
__device__ float  g_bc[TOK*64];       // [B16, C16, dA16, dt16] per token
__device__ __align__(16) __half g_y[TOK*DI];
__device__ float  g_o[TOK*DM];
__device__ float  g_ss[2*TOK];
__device__ __align__(16) __half g_wrnd[NW_IN + NW_OUT];

// ---------------- helpers ---------------------------------------------------
__device__ __forceinline__ float siluf(float x) { return x / (1.f + expf(-x)); }

__device__ __forceinline__ void mma_f16(float* c, const uint32_t* a, const uint32_t* b) {
    asm volatile("mma.sync.aligned.m16n8k16.row.col.f32.f16.f16.f32 "
        "{%0,%1,%2,%3}, {%4,%5,%6,%7}, {%8,%9}, {%0,%1,%2,%3};"
        : "+f"(c[0]), "+f"(c[1]), "+f"(c[2]), "+f"(c[3])
        : "r"(a[0]), "r"(a[1]), "r"(a[2]), "r"(a[3]), "r"(b[0]), "r"(b[1]));
}
__device__ __forceinline__ void cpa16(uint32_t dst, const void* src, int sz) {
    asm volatile("cp.async.ca.shared.global [%0], [%1], 16, %2;"
                 :: "r"(dst), "l"(src), "r"(sz));
}
__device__ __forceinline__ void ldm_x4(uint32_t addr, uint32_t* r) {
    asm volatile("ldmatrix.sync.aligned.m8n8.x4.shared.b16 {%0,%1,%2,%3}, [%4];"
        : "=r"(r[0]), "=r"(r[1]), "=r"(r[2]), "=r"(r[3]) : "r"(addr));
}

// ---------------- FP16 GEMM, 4-stage, ldmatrix, fp32 accum ------------------
__global__ void __launch_bounds__(256, 2)
gemm_f16(const __half* __restrict__ A, const __half* __restrict__ W,
         const float* __restrict__ bias, const float* __restrict__ ssbuf,
         float* __restrict__ C, int M, int N, int K) {
    extern __shared__ __half dsm[];
    const int bm = blockIdx.y * 128, bn = blockIdx.x * 128;
    const int tid = threadIdx.x, lane = tid & 31, warp = tid >> 5;
    const int wm = (warp & 1) * 64, wn = (warp >> 1) * 32;
    const int r0 = lane >> 2, c0 = lane & 3;

    float acc[4][4][4];
#pragma unroll
    for (int i = 0; i < 4; i++)
#pragma unroll
        for (int j = 0; j < 4; j++)
#pragma unroll
            for (int k = 0; k < 4; k++) acc[i][j][k] = 0.f;

    const int lrow = tid >> 1, lch = (tid & 1) * 8;
    const __half* Ap = A + (size_t)(bm + lrow) * K + lch;
    const int bnr = bn + lrow;
    const __half* Bp = W + (size_t)(bnr < N ? bnr : 0) * K + lch;
    const int szb = bnr < N ? 16 : 0;

    const uint32_t base = (uint32_t)__cvta_generic_to_shared(dsm);
    const uint32_t dof = (uint32_t)(lrow * SMH + lch) * 2u;

    const int lane7 = lane & 7;
    const int arow8 = ((lane >> 3) & 1) * 8, acol8 = ((lane >> 4) & 1) * 8;
    const int brow8 = ((lane >> 4) & 1) * 8, bcol8 = ((lane >> 3) & 1) * 8;
    uint32_t aAf[4], aBf[2];
#pragma unroll
    for (int mi = 0; mi < 4; mi++)
        aAf[mi] = base + (uint32_t)(((wm + mi * 16 + lane7 + arow8) * SMH + acol8) * 2);
#pragma unroll
    for (int njp = 0; njp < 2; njp++)
        aBf[njp] = base + 4u * STAGEB +
                   (uint32_t)(((wn + njp * 16 + lane7 + brow8) * SMH + bcol8) * 2);

    const int KT = K >> 4;

#define LOADT(kt, buf)                                                   \
    do {                                                                 \
        int ko = (kt) * 16;                                              \
        uint32_t aA = base + (uint32_t)(buf) * STAGEB;                   \
        uint32_t aB = base + (uint32_t)(4 + (buf)) * STAGEB;             \
        cpa16(aA + dof, Ap + ko, 16);                                    \
        cpa16(aB + dof, Bp + ko, szb);                                   \
        asm volatile("cp.async.commit_group;");                          \
    } while (0)

    LOADT(0, 0);
    if (KT > 1) LOADT(1, 1);
    if (KT > 2) LOADT(2, 2);
    for (int kt = 0; kt < KT; kt++) {
        if (kt < KT - 3) asm volatile("cp.async.wait_group 2;");
        else             asm volatile("cp.async.wait_group 0;");
        __syncthreads();
        if (kt + 3 < KT) LOADT(kt + 3, (kt + 3) & 3);
        const uint32_t cboff = (uint32_t)(kt & 3) * STAGEB;

        uint32_t af[4][4], bf[2][4];
#pragma unroll
        for (int mi = 0; mi < 4; mi++) ldm_x4(aAf[mi] + cboff, af[mi]);
#pragma unroll
        for (int njp = 0; njp < 2; njp++) ldm_x4(aBf[njp] + cboff, bf[njp]);
#pragma unroll
        for (int mi = 0; mi < 4; mi++)
#pragma unroll
            for (int nj = 0; nj < 4; nj++)
                mma_f16(acc[mi][nj], af[mi], &bf[nj >> 1][(nj & 1) * 2]);
    }
#undef LOADT

#pragma unroll
    for (int mi = 0; mi < 4; mi++) {
        int row = bm + wm + mi * 16 + r0;
        float sc0 = 1.f, sc1 = 1.f;
        if (ssbuf != nullptr) {
            sc0 = rsqrtf((ssbuf[row] + ssbuf[M + row]) * (1.f / DI) + 1e-5f);
            sc1 = rsqrtf((ssbuf[row + 8] + ssbuf[M + row + 8]) * (1.f / DI) + 1e-5f);
        }
#pragma unroll
        for (int nj = 0; nj < 4; nj++) {
            int col = bn + wn + nj * 8 + c0 * 2;
            if (col < N) {
                float b0 = 0.f, b1 = 0.f;
                if (bias != nullptr) { b0 = bias[col]; b1 = bias[col + 1]; }
                float2 v0 = make_float2(acc[mi][nj][0] * sc0 + b0, acc[mi][nj][1] * sc0 + b1);
                float2 v1 = make_float2(acc[mi][nj][2] * sc1 + b0, acc[mi][nj][3] * sc1 + b1);
                *(float2*)&C[(size_t)row * N + col] = v0;
                *(float2*)&C[(size_t)(row + 8) * N + col] = v1;
            }
        }
    }
}

// ---------------- weight prep: half-round; fold norm_w into out_proj --------
__global__ void k_prepw(const float* __restrict__ wi, const float* __restrict__ wo,
                        const float* __restrict__ nwp) {
    int idx = blockIdx.x * blockDim.x + threadIdx.x;
    if (idx < NW_IN) {
        g_wrnd[idx] = __float2half_rn(wi[idx]);
    } else if (idx < NW_IN + NW_OUT) {
        int j = idx - NW_IN;
        int l = j / (DM * DI);
        int k = j % DI;
        g_wrnd[idx] = __float2half_rn(wo[j] * nwp[l * DI + k]);
    }
}

// ---------------- encoder ---------------------------------------------------
__global__ void k_sconv(const float* __restrict__ x, const float* __restrict__ w,
                        const float* __restrict__ bias) {
    int c = blockIdx.x, b = blockIdx.y, t = threadIdx.x;
    float v = 0.f;
    if (c < NCH) {
        const float* xr = x + (size_t)(b * NCH + c) * NT;
        float w0 = w[c * 3], w1 = w[c * 3 + 1], w2 = w[c * 3 + 2];
        float xm = (t > 0) ? xr[t - 1] : 0.f;
        float x0 = xr[t];
        float xp = (t < NT - 1) ? xr[t + 1] : 0.f;
        v = xm * w0 + x0 * w1 + xp * w2 + bias[c];
    }
    g_xsr[(size_t)(b * NT + t) * KPAD + c] = __float2half_rn(v);
}

// mixprep + biasenc fold: blocks 0..3 additionally compute mean-emb bias
__global__ void k_mixprep(const float* __restrict__ mw,
                          const float* __restrict__ emb, const float* __restrict__ mb) {
    __shared__ float sb[4][64];
    int idx = blockIdx.x * blockDim.x + threadIdx.x;
    if (idx < DM * KPAD) {
        int d = idx / KPAD, k = idx % KPAD;
        g_mixw[idx] = __float2half_rn((k < NCH) ? mw[d * NCH + k] : 0.f);
    }
    if (blockIdx.x < 4) {
        int d = (blockIdx.x << 6) + (threadIdx.x & 63);
        int cg = threadIdx.x >> 6;
        float s = 0.f;
        for (int c = cg; c < NCH; c += 4) s += emb[c * DM + d];
        sb[cg][threadIdx.x & 63] = s;
        __syncthreads();
        if (threadIdx.x < 64) {
            int dd = (blockIdx.x << 6) + threadIdx.x;
            g_biasenc[dd] = mb[dd] +
                (sb[0][threadIdx.x] + sb[1][threadIdx.x] +
                 sb[2][threadIdx.x] + sb[3][threadIdx.x]) * (1.f / NCH);
        }
    }
}

// ---------------- warp-per-row layernorm: fp32 in (+half res) -> half out ---
union Pk8 { uint4 u; __half h[8]; };

__global__ void k_ln(const float* __restrict__ in, const __half* __restrict__ res,
                     const float* __restrict__ w, const float* __restrict__ b,
                     __half* __restrict__ out) {
    int row = (blockIdx.x * 256 + threadIdx.x) >> 5;
    int lane = threadIdx.x & 31;
    const float4* ip = (const float4*)(in + (size_t)row * DM + lane * 8);
    float4 a0 = ip[0], a1 = ip[1];
    float v[8] = {a0.x, a0.y, a0.z, a0.w, a1.x, a1.y, a1.z, a1.w};
    if (res != nullptr) {
        Pk8 r;
        r.u = *(const uint4*)(res + (size_t)row * DM + lane * 8);
#pragma unroll
        for (int i = 0; i < 8; i++) v[i] += __half2float(r.h[i]);
    }
    float s = 0.f, s2 = 0.f;
#pragma unroll
    for (int i = 0; i < 8; i++) { s += v[i]; s2 = fmaf(v[i], v[i], s2); }
#pragma unroll
    for (int o = 16; o > 0; o >>= 1) {
        s  += __shfl_xor_sync(0xffffffffu, s,  o);
        s2 += __shfl_xor_sync(0xffffffffu, s2, o);
    }
    float mean = s * (1.f / DM);
    float var  = s2 * (1.f / DM) - mean * mean;
    float inv  = rsqrtf(var + 1e-5f);
    const float4* wp = (const float4*)(w + lane * 8);
    const float4* bp = (const float4*)(b + lane * 8);
    float4 w0 = wp[0], w1 = wp[1], b0 = bp[0], b1 = bp[1];
    float wv[8] = {w0.x, w0.y, w0.z, w0.w, w1.x, w1.y, w1.z, w1.w};
    float bv[8] = {b0.x, b0.y, b0.z, b0.w, b1.x, b1.y, b1.z, b1.w};
    Pk8 o8;
#pragma unroll
    for (int i = 0; i < 8; i++)
        o8.h[i] = __float2half_rn((v[i] - mean) * inv * wv[i] + bv[i]);
    *(uint4*)(out + (size_t)row * DM + lane * 8) = o8.u;
}

// -------- B/C conv+silu and dt/dA precompute into g_bc -----------------------
// grid (BB, NT/TSEG), block 256. Output layout per token: [B16, C16, dA16, dt16]
__global__ void k_bc(const float* __restrict__ cw, const float* __restrict__ cb,
                     const float* __restrict__ dtb, const float* __restrict__ alog) {
    const int b = blockIdx.x;
    const int t0 = blockIdx.y * TSEG;
    const int tid = threadIdx.x;
    const float* zb = g_zx + (size_t)(b * NT) * DPROJ;
    for (int i = tid; i < TSEG * 64; i += 256) {
        const int tl = i >> 6, j = i & 63;
        const int t = t0 + tl;
        const int bt = b * NT + t;
        float outv;
        if (j < 32) {                       // B (j<16) / C (16<=j<32) conv channel 512+j
            const int cc = 512 + j;
            float acc = cb[cc];
            const float* wr = cw + cc * 4;
#pragma unroll
            for (int q = 0; q < 4; q++) {
                int tt = t - 3 + q;
                if (tt >= 0) acc = fmaf(zb[(size_t)tt * DPROJ + DI + cc], wr[q], acc);
            }
            outv = siluf(acc);
        } else {
            const int hh = j & 15;
            float raw = zb[(size_t)t * DPROJ + DI + CONVD + hh] + dtb[hh];
            float d = raw > 20.f ? raw : log1pf(expf(raw));
            outv = (j < 48) ? expf(-d * expf(alog[hh])) : d;   // dA then dt
        }
        g_bc[(size_t)bt * 64 + j] = outv;
    }
}

// ---------------- megascan: x-conv+silu+scan+gate+ssq ------------------------
// B/C/dA/dt read precomputed from g_bc (coalesced).
__global__ void k_scan4(const float* __restrict__ cw, const float* __restrict__ cb,
                        const float* __restrict__ Dsk) {
    const int b = blockIdx.x, half = blockIdx.y;
    const int tid = threadIdx.x;                 // 256
    const int h = tid >> 4, p = (tid & 15) + half * 16;
    const int c = h * HD + p;
    const int warp = tid >> 5, lane = tid & 31;
    __shared__ float sB[TTILE][16], sC[TTILE][16];
    __shared__ float sA[TTILE][16], sT[TTILE][16];
    __shared__ float wss[8][NT];

    const float xw0 = cw[c * 4], xw1 = cw[c * 4 + 1];
    const float xw2 = cw[c * 4 + 2], xw3 = cw[c * 4 + 3];
    const float xb = cb[c];
    const float Dh = Dsk[h];
    const int base = b * NT;
    const float* zb = g_zx + (size_t)base * DPROJ;
    const float* bcb = g_bc + (size_t)base * 64;

    float st[DSTATE];
#pragma unroll
    for (int n = 0; n < DSTATE; n++) st[n] = 0.f;
    float hx0 = 0.f, hx1 = 0.f, hx2 = 0.f;

    for (int t0 = 0; t0 < NT; t0 += TTILE) {
        float zg[TTILE], zc[TTILE];
#pragma unroll
        for (int tl = 0; tl < TTILE; tl++) {
            zg[tl] = __ldg(zb + (size_t)(t0 + tl) * DPROJ + c);
            zc[tl] = __ldg(zb + (size_t)(t0 + tl) * DPROJ + DI + c);
        }

        __syncthreads();
        // coalesced stage: 1280 contiguous-per-token floats, 5 per thread
#pragma unroll
        for (int i = tid; i < TTILE * 64; i += 256) {
            const int tl = i >> 6, j = i & 63;
            const float v = __ldg(bcb + (size_t)(t0 + tl) * 64 + j);
            if (j < 16)      sB[tl][j] = v;
            else if (j < 32) sC[tl][j - 16] = v;
            else if (j < 48) sA[tl][j - 32] = v;
            else             sT[tl][j - 48] = v;
        }
        __syncthreads();

#pragma unroll
        for (int tl = 0; tl < TTILE; tl++) {
            const float v3 = zc[tl];
            const float xp = siluf(xb + xw0 * hx0 + xw1 * hx1 + xw2 * hx2 + xw3 * v3);
            hx0 = hx1; hx1 = hx2; hx2 = v3;

            const float dAh = sA[tl][h];
            const float dtx = sT[tl][h] * xp;
            float a0 = 0.f, a1 = 0.f;
#pragma unroll
            for (int n = 0; n < DSTATE; n += 2) {
                st[n]     = fmaf(dAh, st[n],     dtx * sB[tl][n]);
                st[n + 1] = fmaf(dAh, st[n + 1], dtx * sB[tl][n + 1]);
                a0 = fmaf(st[n],     sC[tl][n],     a0);
                a1 = fmaf(st[n + 1], sC[tl][n + 1], a1);
            }
            const __half hv = __float2half_rn((a0 + a1 + xp * Dh) * siluf(zg[tl]));
            g_y[(size_t)(base + t0 + tl) * DI + c] = hv;

            const float ov = __half2float(hv);
            float o2 = ov * ov;
#pragma unroll
            for (int o = 16; o > 0; o >>= 1) o2 += __shfl_xor_sync(0xffffffffu, o2, o);
            if (lane == 0) wss[warp][t0 + tl] = o2;
        }
    }

    __syncthreads();
    for (int t = tid; t < NT; t += 256) {
        float s = 0.f;
#pragma unroll
        for (int w = 0; w < 8; w++) s += wss[w][t];
        g_ss[half * TOK + base + t] = s;
    }
}

// ---------------- fused pool + head ------------------------------------------
__global__ void k_poolhead(const float* __restrict__ w1, const float* __restrict__ b1,
                           const float* __restrict__ w2, const float* __restrict__ b2,
                           float* __restrict__ out) {
    __shared__ float sp[DM];
    __shared__ float sh[4];
    int b = blockIdx.x, tid = threadIdx.x;    // 256
    float s = 0.f;
    for (int t = 0; t < NT; t++) s += __half2float(g_h[(size_t)(b * NT + t) * DM + tid]);
    sp[tid] = s * (1.f / NT);
    __syncthreads();
    if (tid < 128) {
        float acc = b1[tid];
        const float* wr = w1 + tid * DM;
#pragma unroll 8
        for (int k = 0; k < DM; k++) acc = fmaf(sp[k], wr[k], acc);
        float r = fmaxf(acc, 0.f) * w2[tid];
#pragma unroll
        for (int o = 16; o > 0; o >>= 1) r += __shfl_xor_sync(0xffffffffu, r, o);
        int lane = tid & 31, wid = tid >> 5;
        if (lane == 0) sh[wid] = r;
    }
    __syncthreads();
    if (tid == 0) out[b] = sh[0] + sh[1] + sh[2] + sh[3] + b2[0];
}

// ---------------- launch -----------------------------------------------------
extern "C" void kernel_launch(void* const* d_in, const int* in_sizes, int n_in,
                              void* d_out, int out_size) {
    const float* x         = (const float*)d_in[0];
    const float* emb       = (const float*)d_in[1];
    const float* sconv_w   = (const float*)d_in[2];
    const float* sconv_b   = (const float*)d_in[3];
    const float* mixer_w   = (const float*)d_in[4];
    const float* mixer_b   = (const float*)d_in[5];
    const float* enc_ln_w  = (const float*)d_in[6];
    const float* enc_ln_b  = (const float*)d_in[7];
    const float* in_proj_w = (const float*)d_in[8];
    const float* conv_w    = (const float*)d_in[9];
    const float* conv_b    = (const float*)d_in[10];
    const float* dt_bias   = (const float*)d_in[11];
    const float* A_log     = (const float*)d_in[12];
    const float* D_skip    = (const float*)d_in[13];
    const float* norm_w    = (const float*)d_in[14];
    const float* out_proj_w= (const float*)d_in[15];
    const float* ln_w      = (const float*)d_in[16];
    const float* ln_b      = (const float*)d_in[17];
    const float* h1w       = (const float*)d_in[18];
    const float* h1b       = (const float*)d_in[19];
    const float* h2w       = (const float*)d_in[20];
    const float* h2b       = (const float*)d_in[21];
    float* out = (float*)d_out;

    __half *xsr, *mixw, *h, *y, *wrnd;
    float *biasenc, *zx, *o, *ss;
    cudaGetSymbolAddress((void**)&xsr,     g_xsr);
    cudaGetSymbolAddress((void**)&mixw,    g_mixw);
    cudaGetSymbolAddress((void**)&biasenc, g_biasenc);
    cudaGetSymbolAddress((void**)&h,       g_h);
    cudaGetSymbolAddress((void**)&zx,      g_zx);
    cudaGetSymbolAddress((void**)&y,       g_y);
    cudaGetSymbolAddress((void**)&o,       g_o);
    cudaGetSymbolAddress((void**)&wrnd,    g_wrnd);
    cudaGetSymbolAddress((void**)&ss,      g_ss);

    cudaFuncSetAttribute(gemm_f16, cudaFuncAttributeMaxDynamicSharedMemorySize, GSMEM);

    // prep
    k_prepw<<<(NW_IN + NW_OUT + 255) / 256, 256>>>(in_proj_w, out_proj_w, norm_w);
    k_sconv<<<dim3(KPAD, BB), NT>>>(x, sconv_w, sconv_b);
    k_mixprep<<<(DM * KPAD + 255) / 256, 256>>>(mixer_w, emb, mixer_b);

    // encoder: gemm -> o (fp32), ln -> h (half)
    gemm_f16<<<dim3(2, TOK / 128), 256, GSMEM>>>(xsr, mixw, biasenc, nullptr,
                                                 o, TOK, DM, KPAD);
    k_ln<<<TOK / 8, 256>>>(o, nullptr, enc_ln_w, enc_ln_b, h);

    // mamba2 layers
    for (int l = 0; l < NL; l++) {
        gemm_f16<<<dim3((DPROJ + 127) / 128, TOK / 128), 256, GSMEM>>>(
            h, wrnd + (size_t)l * DPROJ * DM, nullptr, nullptr, zx, TOK, DPROJ, DM);
        k_bc<<<dim3(BB, NT / TSEG), 256>>>(conv_w + (size_t)l * CONVD * 4,
                                           conv_b + (size_t)l * CONVD,
                                           dt_bias + l * NH, A_log + l * NH);
        k_scan4<<<dim3(BB, 2), 256>>>(conv_w + (size_t)l * CONVD * 4,
                                      conv_b + (size_t)l * CONVD,
                                      D_skip + l * NH);
        gemm_f16<<<dim3(2, TOK / 128), 256, GSMEM>>>(
            y, wrnd + NW_IN + (size_t)l * DM * DI, nullptr, ss, o, TOK, DM, DI);
        k_ln<<<TOK / 8, 256>>>(o, h, ln_w + l * DM, ln_b + l * DM, h);
    }

    // head
    k_poolhead<<<BB, 256>>>(h1w, h1b, h2w, h2b, out);
}